// round 14
// baseline (speedup 1.0000x reference)
#include <cuda_runtime.h>
#include <math.h>
#include <stdint.h>

// Problem constants
#define B_  4
#define N_  2048
#define D_  1024
#define E_  16
#define C_  256
#define BNEC_ (4LL * 2048 * 16 * 256)   // 33,554,432 elements per output tensor
#define FLT_MIN_NORMAL 1.17549435082228750797e-38f  // 2^-126

#define NLOG_BLOCKS 1024         // 2 halves x 512 (2 tokens/warp)
#define NZERO_BLOCKS 4096
#define NTOPK 64
#define NPROD (NLOG_BLOCKS + NZERO_BLOCKS)      // 5120 producer blocks
#define NTOT  (NPROD + NTOPK)                   // + 64 topk tail blocks
#define HALF_OFF (B_ * E_ * N_)

// Partial logits: [half][b][e][n] (raw dots; topk applies /exp(temp))
__device__ float g_plog[2 * B_ * E_ * N_];
// Cross-block dependency counters (reset by last topk block each launch).
__device__ volatile int g_log_done;
__device__ volatile int g_fill_done;
__device__ int g_reset_cnt;

// ---------------------------------------------------------------------------
// ONE kernel, round-13 K1 geometry preserved exactly:
//  * bids [0,4096): every 4th -> logits (1024), rest -> fill; [4096,5120) fill.
//    (256 threads, 4 blocks/SM, streaming __stcs fill = measured DRAM roofline)
//  * bids [5120,5184): topk+scatter tail blocks (launch LAST, overlap the fill
//    drain; spin on counters instead of a separate 64-block kernel launch,
//    which measured ~6us of pure structural overhead in rounds 4-13).
// ---------------------------------------------------------------------------
__global__ __launch_bounds__(256, 4) void fused_all_kernel(
        const float* __restrict__ key,
        const float* __restrict__ query,
        const float* __restrict__ temp,
        float* __restrict__ out, long long out_n) {
    __shared__ __align__(16) unsigned char smbuf[33920];
    const int bx  = blockIdx.x;
    const int tid = threadIdx.x;
    const int lane = tid & 31;
    const int warp = tid >> 5;

    if (bx < NPROD) {
        const bool is_logits = (bx < 4096) && ((bx & 3) == 0);
        if (!is_logits) {
            // ================= fill role (round-13 verbatim) =================
            int fid = (bx < 4096) ? (3 * (bx >> 2) + (bx & 3) - 1)
                                  : (3072 + (bx - 4096));
            long long n4 = out_n >> 2;
            float4* o4 = reinterpret_cast<float4*>(out);
            long long i = (long long)fid * 256 + tid;
            long long stride = (long long)NZERO_BLOCKS * 256;
            float4 z = make_float4(0.f, 0.f, 0.f, 0.f);
            for (long long k = i; k < n4; k += stride) __stcs(&o4[k], z);
            long long tail = n4 << 2;
            if (i < out_n - tail) out[tail + i] = 0.f;
            __threadfence();
            __syncthreads();
            if (tid == 0) atomicAdd((int*)&g_fill_done, 1);
            return;
        }

        // ================= logits role (round-13 verbatim) =================
        float* sq = (float*)smbuf;                       // 32 KB
        float (*tile)[17] = (float(*)[17])(smbuf + 32768);
        const int lid_blk = bx >> 2;                     // 0..1023
        const int half = lid_blk >> 9;
        const int tok0 = ((lid_blk & 511) * 8 + warp) * 2;

        const float4* kp[2];
        #pragma unroll
        for (int t = 0; t < 2; ++t)
            kp[t] = reinterpret_cast<const float4*>(
                        key + (long long)(tok0 + t) * D_ + half * 512);
        float4 kv[2], kvn[2];
        #pragma unroll
        for (int t = 0; t < 2; ++t) kv[t] = kp[t][lane];

        for (int i = tid; i < E_ * 512; i += 256) {
            int e = i >> 9, j = i & 511;
            sq[i] = query[e * D_ + half * 512 + j];
        }
        __syncthreads();

        float acc[2][E_];
        #pragma unroll
        for (int t = 0; t < 2; t++)
            #pragma unroll
            for (int e = 0; e < E_; e++) acc[t][e] = 0.f;

        const float4* sq4 = reinterpret_cast<const float4*>(sq);
        #pragma unroll
        for (int i = 0; i < 4; ++i) {
            if (i < 3) {
                int dvn = lane + 32 * (i + 1);
                #pragma unroll
                for (int t = 0; t < 2; ++t) kvn[t] = kp[t][dvn];
            }
            int dv = lane + 32 * i;
            #pragma unroll
            for (int e = 0; e < E_; ++e) {
                float4 q = sq4[e * 128 + dv];
                #pragma unroll
                for (int t = 0; t < 2; ++t) {
                    acc[t][e] += kv[t].x * q.x;
                    acc[t][e] += kv[t].y * q.y;
                    acc[t][e] += kv[t].z * q.z;
                    acc[t][e] += kv[t].w * q.w;
                }
            }
            #pragma unroll
            for (int t = 0; t < 2; ++t) kv[t] = kvn[t];
        }

        #pragma unroll
        for (int t = 0; t < 2; ++t) {
            #pragma unroll
            for (int e = 0; e < E_; ++e) {
                float v = acc[t][e];
                #pragma unroll
                for (int off = 16; off > 0; off >>= 1)
                    v += __shfl_xor_sync(0xffffffffu, v, off);
                if (lane == 0) tile[e][warp * 2 + t] = v;
            }
        }
        __syncthreads();

        {
            int base = (lid_blk & 511) * 16;
            int b = base >> 11, n0 = base & (N_ - 1);
            int e = tid >> 4, tk = tid & 15;
            g_plog[half * HALF_OFF + (b * E_ + e) * N_ + n0 + tk] = tile[e][tk];
        }
        __threadfence();
        __syncthreads();
        if (tid == 0) atomicAdd((int*)&g_log_done, 1);
        return;
    }

    // ================= topk + scatter role (256 thr, 8 tokens/thread) ======
    unsigned long long* sk = (unsigned long long*)smbuf;       // 2 KB
    float* redf  = (float*)(smbuf + 2048);                      // 8+8 floats
    int*   wcnt  = (int*)(smbuf + 2176);
    int*   wbase = (int*)(smbuf + 2240);
    int*   mPtr  = (int*)(smbuf + 2304);
    float* af    = (float*)(smbuf + 4096);                      // 8 KB fallback

    const int be = bx - NPROD;            // 0..63
    const int b = be >> 4, e = be & 15;

    // ---- wait for all logits blocks ----
    if (tid == 0) { while (g_log_done < NLOG_BLOCKS) __nanosleep(64); }
    __syncthreads();
    __threadfence();

    const float et = expf(temp[0]);
    const float4* pA = (const float4*)(g_plog + (long long)be * N_);
    const float4* pB = (const float4*)(g_plog + HALF_OFF + (long long)be * N_);
    float xv[8];
    {
        float4 a0 = pA[2 * tid], a1 = pA[2 * tid + 1];
        float4 b0 = pB[2 * tid], b1 = pB[2 * tid + 1];
        xv[0] = (a0.x + b0.x) / et;  xv[1] = (a0.y + b0.y) / et;
        xv[2] = (a0.z + b0.z) / et;  xv[3] = (a0.w + b0.w) / et;
        xv[4] = (a1.x + b1.x) / et;  xv[5] = (a1.y + b1.y) / et;
        xv[6] = (a1.z + b1.z) / et;  xv[7] = (a1.w + b1.w) / et;
    }

    // ---- block max ----
    float mx = xv[0];
    #pragma unroll
    for (int k = 1; k < 8; ++k) mx = fmaxf(mx, xv[k]);
    #pragma unroll
    for (int off = 16; off > 0; off >>= 1)
        mx = fmaxf(mx, __shfl_xor_sync(0xffffffffu, mx, off));
    if (lane == 0) redf[warp] = mx;
    __syncthreads();
    if (tid == 0) {
        float v = redf[0];
        #pragma unroll
        for (int i = 1; i < 8; ++i) v = fmaxf(v, redf[i]);
        redf[8] = v;
    }
    __syncthreads();
    const float m = redf[8];

    // ---- exp (in place) + sum ----
    float s = 0.f;
    #pragma unroll
    for (int k = 0; k < 8; ++k) { xv[k] = expf(xv[k] - m); s += xv[k]; }
    #pragma unroll
    for (int off = 16; off > 0; off >>= 1)
        s += __shfl_xor_sync(0xffffffffu, s, off);
    if (lane == 0) redf[warp] = s;
    __syncthreads();
    if (tid == 0) {
        float v = 0.f;
        #pragma unroll
        for (int i = 0; i < 8; ++i) v += redf[i];
        redf[8] = v;
    }
    __syncthreads();
    const float S = redf[8];

    // ---- normalize (ftz: subnormal affinity -> 0, XLA tie semantics) ----
    int cnt = 0;
    #pragma unroll
    for (int k = 0; k < 8; ++k) {
        float a = xv[k] / S;
        if (a < FLT_MIN_NORMAL) a = 0.f;
        xv[k] = a;
        cnt += (a != 0.f);
    }

    // ---- warp + block exclusive scan of nonzero counts (token order) ----
    int incl = cnt;
    #pragma unroll
    for (int off = 1; off < 32; off <<= 1) {
        int v = __shfl_up_sync(0xffffffffu, incl, off);
        if (lane >= off) incl += v;
    }
    int excl = incl - cnt;
    if (lane == 31) wcnt[warp] = incl;
    __syncthreads();
    if (tid == 0) {
        int acc = 0;
        #pragma unroll
        for (int i = 0; i < 8; ++i) { wbase[i] = acc; acc += wcnt[i]; }
        mPtr[0] = acc;
    }
    __syncthreads();
    const int mNZ = mPtr[0];
    const int nzbase = wbase[warp] + excl;
    const bool hasC = (out_n >= 2 * BNEC_);

    if (mNZ <= C_) {
        // ---- ordered walk: compact nonzero keys; record zero-fill slots ----
        unsigned zlist[8];
        int zw = 0, nzc = nzbase;
        #pragma unroll
        for (int k = 0; k < 8; ++k) {
            int token = 8 * tid + k;
            float a = xv[k];
            if (a != 0.f) {
                sk[nzc] = ((unsigned long long)__float_as_uint(a) << 32)
                        | (unsigned long long)(2047 - token);
                nzc++;
            } else {
                int zr = token - nzc;          // zeros before this token
                if (zr < C_ - mNZ)
                    zlist[zw++] = ((unsigned)(mNZ + zr) << 11) | (unsigned)token;
            }
        }
        __syncthreads();

        // ---- rank-by-counting over the m unique keys ----
        long long offR = -1; float vR = 0.f;
        if (tid < mNZ) {
            unsigned long long K = sk[tid];
            int rank = 0;
            for (int j = 0; j < mNZ; ++j) rank += (sk[j] > K);
            int n = 2047 - (int)(K & 0x7FFu);
            vR = __uint_as_float((unsigned)(K >> 32));
            offR = (((long long)b * N_ + n) * E_ + e) * C_ + rank;
        }

        // ---- wait for the fill, then ALL output writes ----
        if (tid == 0) { while (g_fill_done < NZERO_BLOCKS) __nanosleep(64); }
        __syncthreads();
        __threadfence();

        for (int q = 0; q < zw; ++q) {
            int token = zlist[q] & 0x7FFu;
            int slot  = zlist[q] >> 11;
            out[(((long long)b * N_ + token) * E_ + e) * C_ + slot] = 1.0f;
        }
        if (offR >= 0) {
            out[offR] = 1.0f;
            if (hasC) out[BNEC_ + offR] = vR;
        }
    } else {
        // ---- fallback (m > 256, never on this data): brute-force ranks ----
        #pragma unroll
        for (int k = 0; k < 8; ++k) af[8 * tid + k] = xv[k];
        __syncthreads();
        if (tid == 0) { while (g_fill_done < NZERO_BLOCKS) __nanosleep(64); }
        __syncthreads();
        __threadfence();
        #pragma unroll
        for (int k = 0; k < 8; ++k) {
            int token = 8 * tid + k;
            float ai = xv[k];
            int rank = 0;
            for (int j = 0; j < N_; ++j) {
                float aj = af[j];
                rank += (aj > ai) || (aj == ai && j < token);
            }
            if (rank < C_) {
                long long off = (((long long)b * N_ + token) * E_ + e) * C_ + rank;
                out[off] = 1.0f;
                if (hasC) out[BNEC_ + off] = ai;
            }
        }
    }

    // ---- last topk block resets counters for the next (graph) launch ----
    __syncthreads();
    if (tid == 0) {
        int d = atomicAdd(&g_reset_cnt, 1);
        if (d == NTOPK - 1) {
            g_log_done = 0;
            g_fill_done = 0;
            g_reset_cnt = 0;
        }
    }
}

// ---------------------------------------------------------------------------
extern "C" void kernel_launch(void* const* d_in, const int* in_sizes, int n_in,
                              void* d_out, int out_size) {
    const float* key = nullptr; const float* query = nullptr; const float* temp = nullptr;
    for (int i = 0; i < n_in; ++i) {
        if (in_sizes[i] == B_ * N_ * D_)      key   = (const float*)d_in[i];
        else if (in_sizes[i] == E_ * D_)      query = (const float*)d_in[i];
        else if (in_sizes[i] == 1)            temp  = (const float*)d_in[i];
    }
    if (!key)   key   = (const float*)d_in[0];
    if (!query) query = (const float*)d_in[1];
    if (!temp)  temp  = (const float*)d_in[2];
    float* out = (float*)d_out;

    // Single launch: fill+logits producers (round-13 geometry) + 64 topk tail
    // blocks gated on device counters.
    fused_all_kernel<<<NTOT, 256>>>(key, query, temp, out, (long long)out_size);
}

// round 15
// speedup vs baseline: 1.0705x; 1.0705x over previous
#include <cuda_runtime.h>
#include <math.h>
#include <stdint.h>

// Problem constants
#define B_  4
#define N_  2048
#define D_  1024
#define E_  16
#define C_  256
#define BNEC_ (4LL * 2048 * 16 * 256)   // 33,554,432 elements per output tensor
#define FLT_MIN_NORMAL 1.17549435082228750797e-38f  // 2^-126

#define NLOG_BLOCKS 1024         // 2 halves x 512 (2 tokens/warp)
#define NZERO_BLOCKS 4096
#define NTOT_BLOCKS (NLOG_BLOCKS + NZERO_BLOCKS)
#define NTOPK 64
#define HALF_OFF (B_ * E_ * N_)

// Partial logits: [half][b][e][n] (raw dots; K2 applies /exp(temp))
__device__ float g_plog[2 * B_ * E_ * N_];
// Logits-completion counter (release by K1 logits blocks, acquire by K2;
// reset by the last K2 block each launch for graph-replay determinism).
__device__ volatile int g_log_done;
__device__ int g_reset_cnt;

// ---------------------------------------------------------------------------
// Kernel 1 (round-13 verbatim + PDL trigger + logits release):
//  * blocks [0,4096): every 4th -> logits (1024), rest -> fill; [4096,5120)
//    fill. 256 threads, 4 blocks/SM, streaming __stcs fill (DRAM roofline).
//  * every block triggers the dependent launch at ENTRY, so K2 launches when
//    the last K1 wave starts and overlaps the drain.
//  * only logits blocks fence+count (cheap); fill blocks are untouched —
//    their visibility to K2 comes from cudaGridDependencySynchronize().
// ---------------------------------------------------------------------------
__global__ __launch_bounds__(256, 4) void fused_zero_logits_kernel(
        const float* __restrict__ key,
        const float* __restrict__ query,
        float* __restrict__ out, long long out_n) {
    cudaTriggerProgrammaticLaunchCompletion();

    __shared__ float sq[E_ * 512];   // 32 KB: 16 experts x 512 dims (this half)
    __shared__ float tile[E_][17];   // transpose tile for coalesced writes

    const int bx = blockIdx.x;
    const bool is_logits = (bx < 4096) && ((bx & 3) == 0);

    if (!is_logits) {
        // ---------------- zero-fill path (streaming stores) ----------------
        int fid = (bx < 4096) ? (3 * (bx >> 2) + (bx & 3) - 1)
                              : (3072 + (bx - 4096));
        long long n4 = out_n >> 2;
        float4* o4 = reinterpret_cast<float4*>(out);
        long long i = (long long)fid * 256 + threadIdx.x;
        long long stride = (long long)NZERO_BLOCKS * 256;
        float4 z = make_float4(0.f, 0.f, 0.f, 0.f);
        for (long long k = i; k < n4; k += stride) __stcs(&o4[k], z);
        long long tail = n4 << 2;
        if (i < out_n - tail) out[tail + i] = 0.f;
        return;
    }

    // ---------------- logits path (2 tokens per warp) ----------------
    const int lid_blk = bx >> 2;                          // 0..1023
    const int lane = threadIdx.x & 31;
    const int warp = threadIdx.x >> 5;
    const int half = lid_blk >> 9;                        // dim half 0/1
    const int tok0 = ((lid_blk & 511) * 8 + warp) * 2;

    const float4* kp[2];
    #pragma unroll
    for (int t = 0; t < 2; ++t)
        kp[t] = reinterpret_cast<const float4*>(
                    key + (long long)(tok0 + t) * D_ + half * 512);
    float4 kv[2], kvn[2];
    #pragma unroll
    for (int t = 0; t < 2; ++t) kv[t] = kp[t][lane];

    for (int i = threadIdx.x; i < E_ * 512; i += 256) {
        int e = i >> 9, j = i & 511;
        sq[i] = query[e * D_ + half * 512 + j];
    }
    __syncthreads();

    float acc[2][E_];
    #pragma unroll
    for (int t = 0; t < 2; t++)
        #pragma unroll
        for (int e = 0; e < E_; e++) acc[t][e] = 0.f;

    const float4* sq4 = reinterpret_cast<const float4*>(sq);
    #pragma unroll
    for (int i = 0; i < 4; ++i) {
        if (i < 3) {
            int dvn = lane + 32 * (i + 1);
            #pragma unroll
            for (int t = 0; t < 2; ++t) kvn[t] = kp[t][dvn];
        }
        int dv = lane + 32 * i;
        #pragma unroll
        for (int e = 0; e < E_; ++e) {
            float4 q = sq4[e * 128 + dv];
            #pragma unroll
            for (int t = 0; t < 2; ++t) {
                acc[t][e] += kv[t].x * q.x;
                acc[t][e] += kv[t].y * q.y;
                acc[t][e] += kv[t].z * q.z;
                acc[t][e] += kv[t].w * q.w;
            }
        }
        #pragma unroll
        for (int t = 0; t < 2; ++t) kv[t] = kvn[t];
    }

    #pragma unroll
    for (int t = 0; t < 2; ++t) {
        #pragma unroll
        for (int e = 0; e < E_; ++e) {
            float v = acc[t][e];
            #pragma unroll
            for (int off = 16; off > 0; off >>= 1)
                v += __shfl_xor_sync(0xffffffffu, v, off);
            if (lane == 0) tile[e][warp * 2 + t] = v;
        }
    }
    __syncthreads();

    {
        int base = (lid_blk & 511) * 16;
        int b = base >> 11, n0 = base & (N_ - 1);
        int e = threadIdx.x >> 4, tk = threadIdx.x & 15;
        g_plog[half * HALF_OFF + (b * E_ + e) * N_ + n0 + tk] = tile[e][tk];
    }
    __threadfence();        // release g_plog before counting
    __syncthreads();
    if (threadIdx.x == 0) atomicAdd((int*)&g_log_done, 1);
}

// ---------------------------------------------------------------------------
// Kernel 2 (PDL dependent): launches while K1 drains. Spins on g_log_done,
// runs softmax (ftz, XLA tie semantics) + ordered compaction + rank-by-count
// with all OUT-writes deferred; cudaGridDependencySynchronize() then
// guarantees K1 (incl. fill) is complete and visible; scatter follows.
// ---------------------------------------------------------------------------
__global__ __launch_bounds__(1024) void topk_scatter_kernel(
        const float* __restrict__ temp,
        float* __restrict__ out, long long out_n) {
    __shared__ unsigned long long sk[N_];   // full array only used in fallback
    __shared__ float red[32];
    __shared__ int scnt[64], sbase[64];
    __shared__ int mTot;

    const int be  = blockIdx.x;           // 0..63
    const int b = be / E_, e = be - b * E_;
    const int t = threadIdx.x;
    const int lane = t & 31, w = t >> 5;

    // ---- acquire logits ----
    if (t == 0) { while (g_log_done < NLOG_BLOCKS) __nanosleep(64); }
    __syncthreads();
    __threadfence();

    const float* rowA = g_plog + (long long)be * N_;
    const float* rowB = rowA + HALF_OFF;
    const float et = expf(temp[0]);

    float x0 = (rowA[t] + rowB[t]) / et;
    float x1 = (rowA[t + 1024] + rowB[t + 1024]) / et;

    // ---- block max ----
    float m = fmaxf(x0, x1);
    #pragma unroll
    for (int off = 16; off > 0; off >>= 1)
        m = fmaxf(m, __shfl_xor_sync(0xffffffffu, m, off));
    if (lane == 0) red[w] = m;
    __syncthreads();
    if (t < 32) {
        float v = red[t];
        #pragma unroll
        for (int off = 16; off > 0; off >>= 1)
            v = fmaxf(v, __shfl_xor_sync(0xffffffffu, v, off));
        if (t == 0) red[0] = v;
    }
    __syncthreads();
    m = red[0];
    __syncthreads();

    // ---- exp + sum ----
    float e0 = expf(x0 - m), e1 = expf(x1 - m);
    float s = e0 + e1;
    #pragma unroll
    for (int off = 16; off > 0; off >>= 1)
        s += __shfl_xor_sync(0xffffffffu, s, off);
    if (lane == 0) red[w] = s;
    __syncthreads();
    if (t < 32) {
        float v = red[t];
        #pragma unroll
        for (int off = 16; off > 0; off >>= 1)
            v += __shfl_xor_sync(0xffffffffu, v, off);
        if (t == 0) red[0] = v;
    }
    __syncthreads();
    const float S = red[0];

    // ---- normalize (ftz) ----
    float a0 = e0 / S; if (a0 < FLT_MIN_NORMAL) a0 = 0.f;
    float a1 = e1 / S; if (a1 < FLT_MIN_NORMAL) a1 = 0.f;
    const bool z0 = (a0 == 0.f), z1 = (a1 == 0.f);

    unsigned bal0 = __ballot_sync(0xffffffffu, z0);
    unsigned bal1 = __ballot_sync(0xffffffffu, z1);
    if (lane == 0) { scnt[w] = __popc(bal0); scnt[32 + w] = __popc(bal1); }
    __syncthreads();

    if (t < 32) {
        int c0 = scnt[t], c1 = scnt[t + 32];
        int s0 = c0;
        #pragma unroll
        for (int off = 1; off < 32; off <<= 1) {
            int v = __shfl_up_sync(0xffffffffu, s0, off);
            if (t >= off) s0 += v;
        }
        int tot0 = __shfl_sync(0xffffffffu, s0, 31);
        int s1 = c1;
        #pragma unroll
        for (int off = 1; off < 32; off <<= 1) {
            int v = __shfl_up_sync(0xffffffffu, s1, off);
            if (t >= off) s1 += v;
        }
        sbase[t] = s0 - c0;
        sbase[t + 32] = tot0 + s1 - c1;
        if (t == 31) mTot = 2 * 1024 - (tot0 + s1);
    }
    __syncthreads();
    const int mNZ = mTot;
    const unsigned lmask = (1u << lane) - 1u;
    const int zr0 = sbase[w]      + __popc(bal0 & lmask);
    const int zr1 = sbase[32 + w] + __popc(bal1 & lmask);

    const bool hasC = (out_n >= 2 * BNEC_);

    if (mNZ <= C_) {
        // ---- compact nonzeros ----
        if (!z0) {
            int r = t - zr0;
            sk[r] = ((unsigned long long)__float_as_uint(a0) << 32)
                  | (unsigned long long)(2047 - t);
        }
        if (!z1) {
            int r = (t + 1024) - zr1;
            sk[r] = ((unsigned long long)__float_as_uint(a1) << 32)
                  | (unsigned long long)(2047 - (t + 1024));
        }
        __syncthreads();

        // ---- rank-by-counting (unique keys; order == jax top_k) ----
        long long offR = -1; float vR = 0.f;
        if (t < mNZ) {
            unsigned long long K = sk[t];
            int rank = 0;
            for (int j = 0; j < mNZ; ++j) rank += (sk[j] > K);
            int n = 2047 - (int)(K & 0x7FFu);
            vR = __uint_as_float((unsigned)(K >> 32));
            offR = (((long long)b * N_ + n) * E_ + e) * C_ + rank;
        }
        const bool w0 = z0 && zr0 < C_ - mNZ;
        const bool w1 = z1 && zr1 < C_ - mNZ;

        // ---- wait for K1 (fill) completion, then ALL out-writes ----
        cudaGridDependencySynchronize();

        if (w0)
            out[(((long long)b * N_ + t) * E_ + e) * C_ + (mNZ + zr0)] = 1.0f;
        if (w1)
            out[(((long long)b * N_ + (t + 1024)) * E_ + e) * C_ + (mNZ + zr1)] = 1.0f;
        if (offR >= 0) {
            out[offR] = 1.0f;
            if (hasC) out[BNEC_ + offR] = vR;
        }
    } else {
        // ---- fallback (m > 256): full 2048-key bitonic sort ----
        sk[t]        = ((unsigned long long)__float_as_uint(a0) << 32)
                     | (unsigned long long)(2047 - t);
        sk[t + 1024] = ((unsigned long long)__float_as_uint(a1) << 32)
                     | (unsigned long long)(2047 - (t + 1024));
        __syncthreads();
        for (int k = 2; k <= N_; k <<= 1) {
            for (int j = k >> 1; j > 0; j >>= 1) {
                int i = 2 * t - (t & (j - 1));
                int l = i + j;
                unsigned long long A = sk[i], Bv = sk[l];
                bool dir = ((i & k) == 0);
                bool sw  = dir ? (A < Bv) : (A > Bv);
                if (sw) { sk[i] = Bv; sk[l] = A; }
                __syncthreads();
            }
        }
        cudaGridDependencySynchronize();
        if (t < C_) {
            unsigned long long K = sk[t];
            int   n = 2047 - (int)(K & 0x7FFu);
            float v = __uint_as_float((unsigned int)(K >> 32));
            long long off = (((long long)b * N_ + n) * E_ + e) * C_ + t;
            out[off] = 1.0f;
            if (hasC) out[BNEC_ + off] = v;
        }
    }

    // ---- last block resets the counter for the next (graph) launch ----
    __syncthreads();
    if (t == 0) {
        int d = atomicAdd(&g_reset_cnt, 1);
        if (d == NTOPK - 1) {
            g_log_done = 0;
            g_reset_cnt = 0;
        }
    }
}

// ---------------------------------------------------------------------------
extern "C" void kernel_launch(void* const* d_in, const int* in_sizes, int n_in,
                              void* d_out, int out_size) {
    const float* key = nullptr; const float* query = nullptr; const float* temp = nullptr;
    for (int i = 0; i < n_in; ++i) {
        if (in_sizes[i] == B_ * N_ * D_)      key   = (const float*)d_in[i];
        else if (in_sizes[i] == E_ * D_)      query = (const float*)d_in[i];
        else if (in_sizes[i] == 1)            temp  = (const float*)d_in[i];
    }
    if (!key)   key   = (const float*)d_in[0];
    if (!query) query = (const float*)d_in[1];
    if (!temp)  temp  = (const float*)d_in[2];
    float* out = (float*)d_out;

    // K1: streaming zero-fill + interleaved logits (round-13 proven geometry).
    fused_zero_logits_kernel<<<NTOT_BLOCKS, 256>>>(
        key, query, out, (long long)out_size);

    // K2: PDL dependent launch — starts during K1's final-wave drain.
    cudaLaunchConfig_t cfg = {};
    cfg.gridDim  = dim3(NTOPK, 1, 1);
    cfg.blockDim = dim3(1024, 1, 1);
    cfg.dynamicSmemBytes = 0;
    cfg.stream = 0;
    cudaLaunchAttribute attrs[1];
    attrs[0].id = cudaLaunchAttributeProgrammaticStreamSerialization;
    attrs[0].val.programmaticStreamSerializationAllowed = 1;
    cfg.attrs = attrs;
    cfg.numAttrs = 1;
    cudaError_t err = cudaLaunchKernelEx(&cfg, topk_scatter_kernel,
                                         temp, out, (long long)out_size);
    if (err != cudaSuccess) {
        // Fallback: plain serial launch (identical semantics).
        topk_scatter_kernel<<<NTOPK, 1024>>>(temp, out, (long long)out_size);
    }
}

// round 16
// speedup vs baseline: 1.0989x; 1.0265x over previous
#include <cuda_runtime.h>
#include <math.h>
#include <stdint.h>

// Problem constants
#define B_  4
#define N_  2048
#define D_  1024
#define E_  16
#define C_  256
#define BNEC_ (4LL * 2048 * 16 * 256)   // 33,554,432 elements per output tensor
#define FLT_MIN_NORMAL 1.17549435082228750797e-38f  // 2^-126

#define NPROD 5120               // all producer blocks fill; 1024 also do logits
#define HALF_OFF (B_ * E_ * N_)

// Partial logits: [half][b][e][n] (raw dots; K2 applies /exp(temp))
__device__ float g_plog[2 * B_ * E_ * N_];

// ---------------------------------------------------------------------------
// Kernel 1: ALL 5120 blocks run the grid-stride streaming fill (so no SM slot
// ever idles the store pipe — the round-13 dedicated logits slots cost ~11us
// of store-issue occupancy). Among blocks [0,4096), every 4th block FIRST
// computes its logits chunk (round-13 verbatim math), THEN joins the fill at
// its own stride slot (~2us late start, covered by co-resident blocks).
// ---------------------------------------------------------------------------
__global__ __launch_bounds__(256, 4) void fused_zero_logits_kernel(
        const float* __restrict__ key,
        const float* __restrict__ query,
        float* __restrict__ out, long long out_n) {
    __shared__ float sq[E_ * 512];   // 32 KB: 16 experts x 512 dims (this half)
    __shared__ float tile[E_][17];   // transpose tile for coalesced writes

    const int bx = blockIdx.x;
    const bool is_logits = (bx < 4096) && ((bx & 3) == 0);

    if (is_logits) {
        // ---------------- logits chunk (2 tokens per warp) ----------------
        const int lid_blk = bx >> 2;                      // 0..1023
        const int lane = threadIdx.x & 31;
        const int warp = threadIdx.x >> 5;
        const int half = lid_blk >> 9;                    // dim half 0/1
        const int tok0 = ((lid_blk & 511) * 8 + warp) * 2;

        // Prefetch i=0 key vectors BEFORE the staging sync.
        const float4* kp[2];
        #pragma unroll
        for (int t = 0; t < 2; ++t)
            kp[t] = reinterpret_cast<const float4*>(
                        key + (long long)(tok0 + t) * D_ + half * 512);
        float4 kv[2], kvn[2];
        #pragma unroll
        for (int t = 0; t < 2; ++t) kv[t] = kp[t][lane];

        for (int i = threadIdx.x; i < E_ * 512; i += 256) {
            int e = i >> 9, j = i & 511;
            sq[i] = query[e * D_ + half * 512 + j];
        }
        __syncthreads();

        float acc[2][E_];
        #pragma unroll
        for (int t = 0; t < 2; t++)
            #pragma unroll
            for (int e = 0; e < E_; e++) acc[t][e] = 0.f;

        const float4* sq4 = reinterpret_cast<const float4*>(sq);
        #pragma unroll
        for (int i = 0; i < 4; ++i) {
            if (i < 3) {
                int dvn = lane + 32 * (i + 1);
                #pragma unroll
                for (int t = 0; t < 2; ++t) kvn[t] = kp[t][dvn];
            }
            int dv = lane + 32 * i;
            #pragma unroll
            for (int e = 0; e < E_; ++e) {
                float4 q = sq4[e * 128 + dv];
                #pragma unroll
                for (int t = 0; t < 2; ++t) {
                    acc[t][e] += kv[t].x * q.x;
                    acc[t][e] += kv[t].y * q.y;
                    acc[t][e] += kv[t].z * q.z;
                    acc[t][e] += kv[t].w * q.w;
                }
            }
            #pragma unroll
            for (int t = 0; t < 2; ++t) kv[t] = kvn[t];
        }

        #pragma unroll
        for (int t = 0; t < 2; ++t) {
            #pragma unroll
            for (int e = 0; e < E_; ++e) {
                float v = acc[t][e];
                #pragma unroll
                for (int off = 16; off > 0; off >>= 1)
                    v += __shfl_xor_sync(0xffffffffu, v, off);
                if (lane == 0) tile[e][warp * 2 + t] = v;
            }
        }
        __syncthreads();

        {
            int base = (lid_blk & 511) * 16;
            int b = base >> 11, n0 = base & (N_ - 1);
            int e = threadIdx.x >> 4, tk = threadIdx.x & 15;
            g_plog[half * HALF_OFF + (b * E_ + e) * N_ + n0 + tk] = tile[e][tk];
        }
        // fall through to the fill
    }

    // ---------------- streaming zero-fill (ALL blocks) ----------------
    long long n4 = out_n >> 2;
    float4* o4 = reinterpret_cast<float4*>(out);
    long long i = (long long)bx * 256 + threadIdx.x;
    long long stride = (long long)NPROD * 256;
    float4 z = make_float4(0.f, 0.f, 0.f, 0.f);
    for (long long k = i; k < n4; k += stride) __stcs(&o4[k], z);
    long long tail = n4 << 2;
    if (i < out_n - tail) out[tail + i] = 0.f;
}

// ---------------------------------------------------------------------------
// Kernel 2 (round-13 verbatim, best measured 8.4us): per (b,e) row — softmax
// (ftz on subnormal affinities, XLA tie semantics), SELECT-then-RANK:
//   * nonzero affinities (m ~50) compact in index order into sk[] as packed
//     keys (valbits<<32)|(2047-idx); keys unique;
//   * thread t<m: rank_t = #{j : key_j > key_t} (broadcast LDS, no barriers);
//     rank order == (value desc, index asc) == jax.lax.top_k order;
//   * slots [m,256) zero-affinity tokens ascending-index via ballot scan.
// Fallback full 2048 bitonic sort if m > 256 (not expected).
// ---------------------------------------------------------------------------
__global__ __launch_bounds__(1024) void topk_scatter_kernel(
        const float* __restrict__ temp,
        float* __restrict__ out, long long out_n) {
    __shared__ unsigned long long sk[N_];   // full array only used in fallback
    __shared__ float red[32];
    __shared__ int scnt[64], sbase[64];
    __shared__ int mTot;

    const int be  = blockIdx.x;           // 0..63
    const int b = be / E_, e = be - b * E_;
    const float* rowA = g_plog + (long long)be * N_;
    const float* rowB = rowA + HALF_OFF;
    const int t = threadIdx.x;
    const int lane = t & 31, w = t >> 5;
    const float et = expf(temp[0]);

    float x0 = (rowA[t] + rowB[t]) / et;
    float x1 = (rowA[t + 1024] + rowB[t + 1024]) / et;

    // ---- block max ----
    float m = fmaxf(x0, x1);
    #pragma unroll
    for (int off = 16; off > 0; off >>= 1)
        m = fmaxf(m, __shfl_xor_sync(0xffffffffu, m, off));
    if (lane == 0) red[w] = m;
    __syncthreads();
    if (t < 32) {
        float v = red[t];
        #pragma unroll
        for (int off = 16; off > 0; off >>= 1)
            v = fmaxf(v, __shfl_xor_sync(0xffffffffu, v, off));
        if (t == 0) red[0] = v;
    }
    __syncthreads();
    m = red[0];
    __syncthreads();

    // ---- exp + sum ----
    float e0 = expf(x0 - m), e1 = expf(x1 - m);
    float s = e0 + e1;
    #pragma unroll
    for (int off = 16; off > 0; off >>= 1)
        s += __shfl_xor_sync(0xffffffffu, s, off);
    if (lane == 0) red[w] = s;
    __syncthreads();
    if (t < 32) {
        float v = red[t];
        #pragma unroll
        for (int off = 16; off > 0; off >>= 1)
            v += __shfl_xor_sync(0xffffffffu, v, off);
        if (t == 0) red[0] = v;
    }
    __syncthreads();
    const float S = red[0];

    // ---- normalize (ftz) ----
    float a0 = e0 / S; if (a0 < FLT_MIN_NORMAL) a0 = 0.f;
    float a1 = e1 / S; if (a1 < FLT_MIN_NORMAL) a1 = 0.f;
    const bool z0 = (a0 == 0.f), z1 = (a1 == 0.f);

    unsigned bal0 = __ballot_sync(0xffffffffu, z0);
    unsigned bal1 = __ballot_sync(0xffffffffu, z1);
    if (lane == 0) { scnt[w] = __popc(bal0); scnt[32 + w] = __popc(bal1); }
    __syncthreads();

    // ---- one-warp exclusive scan over the 64 ordered chunks ----
    if (t < 32) {
        int c0 = scnt[t], c1 = scnt[t + 32];
        int s0 = c0;
        #pragma unroll
        for (int off = 1; off < 32; off <<= 1) {
            int v = __shfl_up_sync(0xffffffffu, s0, off);
            if (t >= off) s0 += v;
        }
        int tot0 = __shfl_sync(0xffffffffu, s0, 31);
        int s1 = c1;
        #pragma unroll
        for (int off = 1; off < 32; off <<= 1) {
            int v = __shfl_up_sync(0xffffffffu, s1, off);
            if (t >= off) s1 += v;
        }
        sbase[t] = s0 - c0;
        sbase[t + 32] = tot0 + s1 - c1;
        if (t == 31) mTot = 2 * 1024 - (tot0 + s1);   // # nonzero affinities
    }
    __syncthreads();
    const int mNZ = mTot;
    const unsigned lmask = (1u << lane) - 1u;
    const int zr0 = sbase[w]      + __popc(bal0 & lmask);   // zeros before idx t
    const int zr1 = sbase[32 + w] + __popc(bal1 & lmask);   // zeros before idx t+1024

    const bool hasC = (out_n >= 2 * BNEC_);

    if (mNZ <= C_) {
        // ---- compact nonzeros (index order) ----
        if (!z0) {
            int r = t - zr0;
            sk[r] = ((unsigned long long)__float_as_uint(a0) << 32)
                  | (unsigned long long)(2047 - t);
        }
        if (!z1) {
            int r = (t + 1024) - zr1;
            sk[r] = ((unsigned long long)__float_as_uint(a1) << 32)
                  | (unsigned long long)(2047 - (t + 1024));
        }
        // ---- zero-affinity fill: slot c = m + zero_rank (index ascending) ----
        if (z0 && zr0 < C_ - mNZ) {
            long long off = (((long long)b * N_ + t) * E_ + e) * C_ + (mNZ + zr0);
            out[off] = 1.0f;                 // combine = 0, already zeroed
        }
        if (z1 && zr1 < C_ - mNZ) {
            long long off = (((long long)b * N_ + (t + 1024)) * E_ + e) * C_ + (mNZ + zr1);
            out[off] = 1.0f;
        }
        __syncthreads();

        // ---- rank-by-counting over the m unique keys (no barriers) ----
        if (t < mNZ) {
            unsigned long long K = sk[t];
            int rank = 0;
            for (int j = 0; j < mNZ; ++j)
                rank += (sk[j] > K);
            int   n = 2047 - (int)(K & 0x7FFu);
            float v = __uint_as_float((unsigned int)(K >> 32));
            long long off = (((long long)b * N_ + n) * E_ + e) * C_ + rank;
            out[off] = 1.0f;
            if (hasC) out[BNEC_ + off] = v;
        }
    } else {
        // ---- fallback (m > 256): full 2048-key bitonic sort ----
        sk[t]        = ((unsigned long long)__float_as_uint(a0) << 32)
                     | (unsigned long long)(2047 - t);
        sk[t + 1024] = ((unsigned long long)__float_as_uint(a1) << 32)
                     | (unsigned long long)(2047 - (t + 1024));
        __syncthreads();
        for (int k = 2; k <= N_; k <<= 1) {
            for (int j = k >> 1; j > 0; j >>= 1) {
                int i = 2 * t - (t & (j - 1));
                int l = i + j;
                unsigned long long A = sk[i], Bv = sk[l];
                bool dir = ((i & k) == 0);
                bool sw  = dir ? (A < Bv) : (A > Bv);
                if (sw) { sk[i] = Bv; sk[l] = A; }
                __syncthreads();
            }
        }
        if (t < C_) {
            unsigned long long K = sk[t];
            int   n = 2047 - (int)(K & 0x7FFu);
            float v = __uint_as_float((unsigned int)(K >> 32));
            long long off = (((long long)b * N_ + n) * E_ + e) * C_ + t;
            out[off] = 1.0f;
            if (hasC) out[BNEC_ + off] = v;
        }
    }
}

// ---------------------------------------------------------------------------
extern "C" void kernel_launch(void* const* d_in, const int* in_sizes, int n_in,
                              void* d_out, int out_size) {
    const float* key = nullptr; const float* query = nullptr; const float* temp = nullptr;
    for (int i = 0; i < n_in; ++i) {
        if (in_sizes[i] == B_ * N_ * D_)      key   = (const float*)d_in[i];
        else if (in_sizes[i] == E_ * D_)      query = (const float*)d_in[i];
        else if (in_sizes[i] == 1)            temp  = (const float*)d_in[i];
    }
    if (!key)   key   = (const float*)d_in[0];
    if (!query) query = (const float*)d_in[1];
    if (!temp)  temp  = (const float*)d_in[2];
    float* out = (float*)d_out;

    // K1: 5120 blocks, ALL fill; 1024 of them do their logits chunk first.
    fused_zero_logits_kernel<<<NPROD, 256>>>(
        key, query, out, (long long)out_size);
    // K2: softmax + select-then-RANK top-256 + direct scatter.
    topk_scatter_kernel<<<B_ * E_, 1024>>>(temp, out, (long long)out_size);
}